// round 2
// baseline (speedup 1.0000x reference)
#include <cuda_runtime.h>
#include <cuda_bf16.h>
#include <math.h>

// Problem constants (fixed by the reference setup)
#define BATCH    32
#define SRC_LEN  2048
#define DIM      1024            // enc feature dim == dec_hid_dim
#define WARPS_PER_BLOCK 8
#define BLOCK_THREADS   (WARPS_PER_BLOCK * 32)
#define SCORE_GRID      888      // 148 SMs * 6 resident blocks
#define TOTAL_ROWS      (SRC_LEN * BATCH)   // 65536

// ---------------------------------------------------------------------------
// Kernel 1 (score): out[b, s] = enc_outputs[s,b,:] . w_enc        (RAW score)
// Persistent grid-stride: one warp per (s,b) row per iteration.
// w_enc staged in shared once per block (888 blocks -> ~3.5 MB W traffic).
// tanh / e_dec / bias are applied later in the softmax kernel.
// ---------------------------------------------------------------------------
__global__ void __launch_bounds__(BLOCK_THREADS)
score_kernel(const float* __restrict__ enc_outputs,
             const float* __restrict__ W,
             float* __restrict__ out)
{
    __shared__ float4 s_wenc[DIM / 4];   // 4 KB

    const float4* we_g = reinterpret_cast<const float4*>(W + DIM);
    for (int i = threadIdx.x; i < DIM / 4; i += BLOCK_THREADS)
        s_wenc[i] = we_g[i];
    __syncthreads();

    const int warp = threadIdx.x >> 5;
    const int lane = threadIdx.x & 31;
    const int warp_global  = blockIdx.x * WARPS_PER_BLOCK + warp;
    const int total_warps  = SCORE_GRID * WARPS_PER_BLOCK;      // 7104

    // Pre-load this lane's slice of w_enc into registers (reused every row)
    float4 w[8];
#pragma unroll
    for (int i = 0; i < 8; ++i)
        w[i] = s_wenc[lane + i * 32];

    for (int flat = warp_global; flat < TOTAL_ROWS; flat += total_warps) {
        // enc layout [s][b][e], flat = s*32 + b exactly
        const float4* row = reinterpret_cast<const float4*>(
            enc_outputs + (size_t)flat * DIM);

        float acc = 0.f;
#pragma unroll
        for (int i = 0; i < 8; ++i) {             // 8 independent float4 loads
            float4 v = row[lane + i * 32];
            acc += v.x * w[i].x + v.y * w[i].y + v.z * w[i].z + v.w * w[i].w;
        }
#pragma unroll
        for (int o = 16; o > 0; o >>= 1)
            acc += __shfl_xor_sync(0xFFFFFFFFu, acc, o);

        if (lane == 0) {
            int s = flat >> 5;
            int b = flat & 31;
            out[(size_t)b * SRC_LEN + s] = acc;   // raw score
        }
    }
}

// ---------------------------------------------------------------------------
// Kernel 2: per-batch-row  e_dec + bias + tanh + softmax, in place.
// One block per b (32 blocks, 256 threads). Row of 2048 in registers.
// ---------------------------------------------------------------------------
#define SM_THREADS 256
#define SM_VPT     (SRC_LEN / SM_THREADS)   // 8 values per thread

__global__ void __launch_bounds__(SM_THREADS)
softmax_kernel(const float* __restrict__ dec_hidden,
               const float* __restrict__ W,
               const float* __restrict__ bias,
               float* __restrict__ out)
{
    __shared__ float red[SM_THREADS / 32];

    const int b    = blockIdx.x;
    const int tid  = threadIdx.x;
    const int lane = tid & 31;
    const int warp = tid >> 5;

    // ---- e_dec[b] = dec_hidden[b,:] . W[0,0:1024] ----
    const float4* dh = reinterpret_cast<const float4*>(dec_hidden + (size_t)b * DIM);
    const float4* wd = reinterpret_cast<const float4*>(W);
    float ed = 0.f;
    {   // 256 threads x 1 float4 each covers 1024 floats
        float4 v = dh[tid];
        float4 wv = wd[tid];
        ed = v.x * wv.x + v.y * wv.y + v.z * wv.z + v.w * wv.w;
    }
#pragma unroll
    for (int o = 16; o > 0; o >>= 1)
        ed += __shfl_xor_sync(0xFFFFFFFFu, ed, o);
    if (lane == 0) red[warp] = ed;
    __syncthreads();
    if (warp == 0) {
        float t = (lane < SM_THREADS / 32) ? red[lane] : 0.f;
#pragma unroll
        for (int o = 16; o > 0; o >>= 1)
            t += __shfl_xor_sync(0xFFFFFFFFu, t, o);
        if (lane == 0) red[0] = t;
    }
    __syncthreads();
    const float edec_b = red[0] + bias[0];
    __syncthreads();

    // ---- load row, apply tanh, softmax ----
    float* row = out + (size_t)b * SRC_LEN;

    float v[SM_VPT];
    float m = -INFINITY;
#pragma unroll
    for (int i = 0; i < SM_VPT; ++i) {
        v[i] = tanhf(row[tid + i * SM_THREADS] + edec_b);
        m = fmaxf(m, v[i]);
    }
    // block max
#pragma unroll
    for (int o = 16; o > 0; o >>= 1)
        m = fmaxf(m, __shfl_xor_sync(0xFFFFFFFFu, m, o));
    if (lane == 0) red[warp] = m;
    __syncthreads();
    if (warp == 0) {
        float t = (lane < SM_THREADS / 32) ? red[lane] : -INFINITY;
#pragma unroll
        for (int o = 16; o > 0; o >>= 1)
            t = fmaxf(t, __shfl_xor_sync(0xFFFFFFFFu, t, o));
        if (lane == 0) red[0] = t;
    }
    __syncthreads();
    m = red[0];
    __syncthreads();

    float sum = 0.f;
#pragma unroll
    for (int i = 0; i < SM_VPT; ++i) {
        v[i] = __expf(v[i] - m);
        sum += v[i];
    }
    // block sum
#pragma unroll
    for (int o = 16; o > 0; o >>= 1)
        sum += __shfl_xor_sync(0xFFFFFFFFu, sum, o);
    if (lane == 0) red[warp] = sum;
    __syncthreads();
    if (warp == 0) {
        float t = (lane < SM_THREADS / 32) ? red[lane] : 0.f;
#pragma unroll
        for (int o = 16; o > 0; o >>= 1)
            t += __shfl_xor_sync(0xFFFFFFFFu, t, o);
        if (lane == 0) red[0] = t;
    }
    __syncthreads();
    const float inv = 1.0f / red[0];

#pragma unroll
    for (int i = 0; i < SM_VPT; ++i)
        row[tid + i * SM_THREADS] = v[i] * inv;
}

// ---------------------------------------------------------------------------
extern "C" void kernel_launch(void* const* d_in, const int* in_sizes, int n_in,
                              void* d_out, int out_size)
{
    const float* dec_hidden  = (const float*)d_in[0];   // (32, 1024)
    const float* enc_outputs = (const float*)d_in[1];   // (2048, 32, 1024)
    const float* W           = (const float*)d_in[2];   // (1, 2048)
    const float* bias        = (const float*)d_in[3];   // (1,)
    float* out = (float*)d_out;                          // (32, 2048)

    score_kernel<<<SCORE_GRID, BLOCK_THREADS>>>(enc_outputs, W, out);
    softmax_kernel<<<BATCH, SM_THREADS>>>(dec_hidden, W, bias, out);
}

// round 3
// speedup vs baseline: 1.0573x; 1.0573x over previous
#include <cuda_runtime.h>
#include <cuda_bf16.h>
#include <math.h>

// Problem constants (fixed by the reference setup)
#define BATCH    32
#define SRC_LEN  2048
#define DIM      1024
#define TOTAL_ROWS (SRC_LEN * BATCH)        // 65536

#define WARPS_PER_BLOCK 8
#define BLOCK_THREADS   (WARPS_PER_BLOCK * 32)
#define ROWS_PER_WARP   2
#define SCORE_BLOCKS    (TOTAL_ROWS / ROWS_PER_WARP / WARPS_PER_BLOCK)  // 4096

// ---------------------------------------------------------------------------
// Kernel 1 (score): out[b, s] = enc_outputs[s,b,:] . w_enc      (RAW score)
// Flat grid, 2 rows per warp -> 16 independent float4 loads per lane.
// ---------------------------------------------------------------------------
__global__ void __launch_bounds__(BLOCK_THREADS)
score_kernel(const float* __restrict__ enc_outputs,
             const float* __restrict__ W,
             float* __restrict__ out)
{
    __shared__ float4 s_wenc[DIM / 4];   // 4 KB

    const float4* we_g = reinterpret_cast<const float4*>(W + DIM);
    for (int i = threadIdx.x; i < DIM / 4; i += BLOCK_THREADS)
        s_wenc[i] = we_g[i];
    __syncthreads();

    const int warp = threadIdx.x >> 5;
    const int lane = threadIdx.x & 31;
    const int pair = blockIdx.x * WARPS_PER_BLOCK + warp;  // 0 .. 32767
    const int flat0 = pair * 2;
    const int flat1 = flat0 + 1;

    const float4* r0 = reinterpret_cast<const float4*>(enc_outputs + (size_t)flat0 * DIM);
    const float4* r1 = reinterpret_cast<const float4*>(enc_outputs + (size_t)flat1 * DIM);

    float acc0 = 0.f, acc1 = 0.f;
#pragma unroll
    for (int i = 0; i < 8; ++i) {
        float4 w = s_wenc[lane + i * 32];
        float4 a = r0[lane + i * 32];
        float4 b = r1[lane + i * 32];
        acc0 += a.x * w.x + a.y * w.y + a.z * w.z + a.w * w.w;
        acc1 += b.x * w.x + b.y * w.y + b.z * w.z + b.w * w.w;
    }
#pragma unroll
    for (int o = 16; o > 0; o >>= 1) {
        acc0 += __shfl_xor_sync(0xFFFFFFFFu, acc0, o);
        acc1 += __shfl_xor_sync(0xFFFFFFFFu, acc1, o);
    }

    if (lane == 0) {
        int s0 = flat0 >> 5, b0 = flat0 & 31;
        int s1 = flat1 >> 5, b1 = flat1 & 31;
        out[(size_t)b0 * SRC_LEN + s0] = acc0;   // raw score
        out[(size_t)b1 * SRC_LEN + s1] = acc1;
    }
}

// ---------------------------------------------------------------------------
// Kernel 2: per-batch-row  e_dec + bias + tanh + softmax, in place.
// tanh output is in [-1,1] so exp cannot overflow -> NO max pass needed.
// One block per b (32 blocks, 512 threads).
// ---------------------------------------------------------------------------
#define SM_THREADS 512
#define SM_VPT     (SRC_LEN / SM_THREADS)   // 4 values per thread
#define SM_WARPS   (SM_THREADS / 32)        // 16

__global__ void __launch_bounds__(SM_THREADS)
softmax_kernel(const float* __restrict__ dec_hidden,
               const float* __restrict__ W,
               const float* __restrict__ bias,
               float* __restrict__ out)
{
    __shared__ float red[SM_WARPS];

    const int b    = blockIdx.x;
    const int tid  = threadIdx.x;
    const int lane = tid & 31;
    const int warp = tid >> 5;

    float* row = out + (size_t)b * SRC_LEN;

    // Issue the row loads early (independent of e_dec computation)
    float v[SM_VPT];
#pragma unroll
    for (int i = 0; i < SM_VPT; ++i)
        v[i] = row[tid + i * SM_THREADS];

    // ---- e_dec[b] = dec_hidden[b,:] . W[0,0:1024] ----  (512 thr x float2)
    const float2* dh = reinterpret_cast<const float2*>(dec_hidden + (size_t)b * DIM);
    const float2* wd = reinterpret_cast<const float2*>(W);
    float2 dv = dh[tid];
    float2 wv = wd[tid];
    float ed = dv.x * wv.x + dv.y * wv.y;
#pragma unroll
    for (int o = 16; o > 0; o >>= 1)
        ed += __shfl_xor_sync(0xFFFFFFFFu, ed, o);
    if (lane == 0) red[warp] = ed;
    __syncthreads();
    if (warp == 0) {
        float t = (lane < SM_WARPS) ? red[lane] : 0.f;
#pragma unroll
        for (int o = 16; o > 0; o >>= 1)
            t += __shfl_xor_sync(0xFFFFFFFFu, t, o);
        if (lane == 0) red[0] = t;
    }
    __syncthreads();
    const float edec_b = red[0] + bias[0];
    __syncthreads();

    // ---- tanh + exp + sum (no max subtraction needed: tanh in [-1,1]) ----
    float sum = 0.f;
#pragma unroll
    for (int i = 0; i < SM_VPT; ++i) {
        v[i] = __expf(tanhf(v[i] + edec_b));
        sum += v[i];
    }
#pragma unroll
    for (int o = 16; o > 0; o >>= 1)
        sum += __shfl_xor_sync(0xFFFFFFFFu, sum, o);
    if (lane == 0) red[warp] = sum;
    __syncthreads();
    if (warp == 0) {
        float t = (lane < SM_WARPS) ? red[lane] : 0.f;
#pragma unroll
        for (int o = 16; o > 0; o >>= 1)
            t += __shfl_xor_sync(0xFFFFFFFFu, t, o);
        if (lane == 0) red[0] = t;
    }
    __syncthreads();
    const float inv = 1.0f / red[0];

#pragma unroll
    for (int i = 0; i < SM_VPT; ++i)
        row[tid + i * SM_THREADS] = v[i] * inv;
}

// ---------------------------------------------------------------------------
extern "C" void kernel_launch(void* const* d_in, const int* in_sizes, int n_in,
                              void* d_out, int out_size)
{
    const float* dec_hidden  = (const float*)d_in[0];   // (32, 1024)
    const float* enc_outputs = (const float*)d_in[1];   // (2048, 32, 1024)
    const float* W           = (const float*)d_in[2];   // (1, 2048)
    const float* bias        = (const float*)d_in[3];   // (1,)
    float* out = (float*)d_out;                          // (32, 2048)

    score_kernel<<<SCORE_BLOCKS, BLOCK_THREADS>>>(enc_outputs, W, out);
    softmax_kernel<<<BATCH, SM_THREADS>>>(dec_hidden, W, bias, out);
}